// round 1
// baseline (speedup 1.0000x reference)
#include <cuda_runtime.h>

#define IN_F   128
#define OUT_F  64
#define ALPHA  0.2f
#define LN_EPS 1e-5f
#define MAXN   100352   // padded above N=100000

// Scratch (device globals — no allocation allowed)
__device__ float g_h [MAXN * OUT_F];   // h = x@W^T + b
__device__ float g_sl[MAXN];           // h @ a[:64]
__device__ float g_sr[MAXN];           // h @ a[64:]

// ---------------------------------------------------------------------------
// Zero the output accumulator (d_out is poisoned each run)
// ---------------------------------------------------------------------------
__global__ void zero_kernel(float4* __restrict__ p, int n4) {
    int i = blockIdx.x * blockDim.x + threadIdx.x;
    if (i < n4) p[i] = make_float4(0.f, 0.f, 0.f, 0.f);
}

// ---------------------------------------------------------------------------
// GEMM: h[n,64] = x[n,128] @ W[64,128]^T + b
// Block: 256 threads, tile 64 rows x 64 cols, 4x4 register micro-tile.
// ---------------------------------------------------------------------------
__global__ __launch_bounds__(256) void gemm_kernel(
    const float* __restrict__ x, const float* __restrict__ W,
    const float* __restrict__ b, int n)
{
    __shared__ float xs[64][IN_F + 4];    // +4 pad: conflict-free row reads
    __shared__ float ws[OUT_F][IN_F + 1]; // +1 pad

    const int tid  = threadIdx.x;
    const int row0 = blockIdx.x * 64;

    for (int i = tid; i < OUT_F * IN_F; i += 256)
        ws[i >> 7][i & 127] = W[i];
    for (int i = tid; i < 64 * IN_F; i += 256) {
        int r = i >> 7, k = i & 127;
        int gr = row0 + r;
        xs[r][k] = (gr < n) ? x[(size_t)gr * IN_F + k] : 0.f;
    }
    __syncthreads();

    const int tx = tid & 15;   // col group (tx*4 .. tx*4+3)
    const int ty = tid >> 4;   // row group (ty*4 .. ty*4+3)

    float acc[4][4];
#pragma unroll
    for (int i = 0; i < 4; i++)
#pragma unroll
        for (int j = 0; j < 4; j++) acc[i][j] = 0.f;

#pragma unroll 8
    for (int k = 0; k < IN_F; k++) {
        float xv[4], wv[4];
#pragma unroll
        for (int i = 0; i < 4; i++) xv[i] = xs[ty * 4 + i][k];
#pragma unroll
        for (int j = 0; j < 4; j++) wv[j] = ws[tx * 4 + j][k];
#pragma unroll
        for (int i = 0; i < 4; i++)
#pragma unroll
            for (int j = 0; j < 4; j++) acc[i][j] = fmaf(xv[i], wv[j], acc[i][j]);
    }

    float b0 = b[tx * 4 + 0], b1 = b[tx * 4 + 1],
          b2 = b[tx * 4 + 2], b3 = b[tx * 4 + 3];

#pragma unroll
    for (int i = 0; i < 4; i++) {
        int gr = row0 + ty * 4 + i;
        if (gr < n) {
            float4 o;
            o.x = acc[i][0] + b0;
            o.y = acc[i][1] + b1;
            o.z = acc[i][2] + b2;
            o.w = acc[i][3] + b3;
            *reinterpret_cast<float4*>(&g_h[(size_t)gr * OUT_F + tx * 4]) = o;
        }
    }
}

// ---------------------------------------------------------------------------
// Per-node attention halves: sl = h . a[:64], sr = h . a[64:]
// One warp per node, float2 per lane.
// ---------------------------------------------------------------------------
__global__ __launch_bounds__(256) void slsr_kernel(
    const float* __restrict__ a, int n)
{
    int warp = (blockIdx.x * blockDim.x + threadIdx.x) >> 5;
    int lane = threadIdx.x & 31;
    if (warp >= n) return;

    float2 hv = *reinterpret_cast<const float2*>(&g_h[(size_t)warp * OUT_F + lane * 2]);
    float2 al = *reinterpret_cast<const float2*>(&a[lane * 2]);
    float2 ar = *reinterpret_cast<const float2*>(&a[OUT_F + lane * 2]);

    float s1 = hv.x * al.x + hv.y * al.y;
    float s2 = hv.x * ar.x + hv.y * ar.y;
#pragma unroll
    for (int o = 16; o; o >>= 1) {
        s1 += __shfl_xor_sync(0xFFFFFFFFu, s1, o);
        s2 += __shfl_xor_sync(0xFFFFFFFFu, s2, o);
    }
    if (lane == 0) { g_sl[warp] = s1; g_sr[warp] = s2; }
}

// ---------------------------------------------------------------------------
// Edge aggregation: out[src] += exp(-lrelu(sl[src]+sr[dst])) * h[dst]
// 16 threads per edge, one float4 vector-reduction each.
// ---------------------------------------------------------------------------
__global__ __launch_bounds__(256) void edge_kernel(
    const int* __restrict__ edge, float* __restrict__ hp, int E)
{
    long long t = (long long)blockIdx.x * blockDim.x + threadIdx.x;
    int e = (int)(t >> 4);
    int g = (int)(t & 15);
    if (e >= E) return;

    int s = __ldg(&edge[e]);
    int d = __ldg(&edge[E + e]);

    float sc = __ldg(&g_sl[s]) + __ldg(&g_sr[d]);
    float lr = sc > 0.f ? sc : ALPHA * sc;
    float w  = __expf(-lr);

    float4 hv = *reinterpret_cast<const float4*>(&g_h[(size_t)d * OUT_F + g * 4]);
    float* dst = &hp[(size_t)s * OUT_F + g * 4];

    asm volatile("red.global.add.v4.f32 [%0], {%1, %2, %3, %4};"
                 :: "l"(dst), "f"(w * hv.x), "f"(w * hv.y),
                    "f"(w * hv.z), "f"(w * hv.w)
                 : "memory");
}

// ---------------------------------------------------------------------------
// LayerNorm (biased var) + ELU, in place on out. One warp per row.
// ---------------------------------------------------------------------------
__global__ __launch_bounds__(256) void ln_elu_kernel(
    float* __restrict__ out, const float* __restrict__ gamma,
    const float* __restrict__ beta, int n)
{
    int warp = (blockIdx.x * blockDim.x + threadIdx.x) >> 5;
    int lane = threadIdx.x & 31;
    if (warp >= n) return;

    float2 v = *reinterpret_cast<const float2*>(&out[(size_t)warp * OUT_F + lane * 2]);

    // pass 1: mean
    float s = v.x + v.y;
#pragma unroll
    for (int o = 16; o; o >>= 1) s += __shfl_xor_sync(0xFFFFFFFFu, s, o);
    float mu = s * (1.f / OUT_F);

    // pass 2: variance of centered values (avoids cancellation)
    float c0 = v.x - mu, c1 = v.y - mu;
    float q = c0 * c0 + c1 * c1;
#pragma unroll
    for (int o = 16; o; o >>= 1) q += __shfl_xor_sync(0xFFFFFFFFu, q, o);
    float rs = rsqrtf(q * (1.f / OUT_F) + LN_EPS);

    float2 gg = *reinterpret_cast<const float2*>(&gamma[lane * 2]);
    float2 bb = *reinterpret_cast<const float2*>(&beta[lane * 2]);

    float y0 = c0 * rs * gg.x + bb.x;
    float y1 = c1 * rs * gg.y + bb.y;
    y0 = y0 > 0.f ? y0 : expm1f(y0);   // ELU(alpha=1)
    y1 = y1 > 0.f ? y1 : expm1f(y1);

    float2 o2; o2.x = y0; o2.y = y1;
    *reinterpret_cast<float2*>(&out[(size_t)warp * OUT_F + lane * 2]) = o2;
}

// ---------------------------------------------------------------------------
extern "C" void kernel_launch(void* const* d_in, const int* in_sizes, int n_in,
                              void* d_out, int out_size)
{
    const float* x     = (const float*)d_in[0];
    const int*   edge  = (const int*)  d_in[1];
    const float* W     = (const float*)d_in[2];
    const float* b     = (const float*)d_in[3];
    const float* a     = (const float*)d_in[4];
    const float* gamma = (const float*)d_in[5];
    const float* beta  = (const float*)d_in[6];
    float* out = (float*)d_out;

    const int n = in_sizes[0] / IN_F;   // 100000
    const int E = in_sizes[1] / 2;      // 3200000

    // 1. zero output accumulator
    int n4 = (n * OUT_F) / 4;
    zero_kernel<<<(n4 + 255) / 256, 256>>>((float4*)out, n4);

    // 2. h = x @ W^T + b
    gemm_kernel<<<(n + 63) / 64, 256>>>(x, W, b, n);

    // 3. sl / sr per node
    slsr_kernel<<<(n + 7) / 8, 256>>>(a, n);

    // 4. edge scatter-aggregate into out
    long long et = (long long)E * 16;
    edge_kernel<<<(unsigned)((et + 255) / 256), 256>>>(edge, out, E);

    // 5. LayerNorm + ELU in place
    ln_elu_kernel<<<(n + 7) / 8, 256>>>(out, gamma, beta, n);
}

// round 2
// speedup vs baseline: 1.1868x; 1.1868x over previous
#include <cuda_runtime.h>

#define IN_F   128
#define OUT_F  64
#define ALPHA  0.2f
#define LN_EPS 1e-5f
#define MAXN   100352    // padded above N=100000 (multiple of 1024)
#define EMAX   3276800   // padded above E=3200000

// Scratch (device globals — no allocation allowed)
__device__ float  g_h [MAXN * OUT_F];  // h = x@W^T + b
__device__ float  g_sl[MAXN];          // h @ a[:64]
__device__ float  g_sr[MAXN];          // h @ a[64:]
__device__ int    g_cnt[MAXN];         // per-src edge counts
__device__ int    g_off[MAXN];         // exclusive prefix (CSR row ptr)
__device__ int    g_cur[MAXN];         // scatter cursors (copy of g_off)
__device__ int    g_bsum[128];         // block sums for scan
__device__ float2 g_adj[EMAX];         // CSR payload: {dst (int bits), weight}

// ---------------------------------------------------------------------------
// Zero per-src counters
// ---------------------------------------------------------------------------
__global__ void zero_cnt_kernel(int n) {
    int i = blockIdx.x * blockDim.x + threadIdx.x;
    if (i < n) g_cnt[i] = 0;
}

// ---------------------------------------------------------------------------
// GEMM: h[n,64] = x[n,128] @ W[64,128]^T + b
// ---------------------------------------------------------------------------
__global__ __launch_bounds__(256) void gemm_kernel(
    const float* __restrict__ x, const float* __restrict__ W,
    const float* __restrict__ b, int n)
{
    __shared__ float xs[64][IN_F + 4];
    __shared__ float ws[OUT_F][IN_F + 1];

    const int tid  = threadIdx.x;
    const int row0 = blockIdx.x * 64;

    for (int i = tid; i < OUT_F * IN_F; i += 256)
        ws[i >> 7][i & 127] = W[i];
    for (int i = tid; i < 64 * IN_F; i += 256) {
        int r = i >> 7, k = i & 127;
        int gr = row0 + r;
        xs[r][k] = (gr < n) ? x[(size_t)gr * IN_F + k] : 0.f;
    }
    __syncthreads();

    const int tx = tid & 15;
    const int ty = tid >> 4;

    float acc[4][4];
#pragma unroll
    for (int i = 0; i < 4; i++)
#pragma unroll
        for (int j = 0; j < 4; j++) acc[i][j] = 0.f;

#pragma unroll 8
    for (int k = 0; k < IN_F; k++) {
        float xv[4], wv[4];
#pragma unroll
        for (int i = 0; i < 4; i++) xv[i] = xs[ty * 4 + i][k];
#pragma unroll
        for (int j = 0; j < 4; j++) wv[j] = ws[tx * 4 + j][k];
#pragma unroll
        for (int i = 0; i < 4; i++)
#pragma unroll
            for (int j = 0; j < 4; j++) acc[i][j] = fmaf(xv[i], wv[j], acc[i][j]);
    }

    float b0 = b[tx * 4 + 0], b1 = b[tx * 4 + 1],
          b2 = b[tx * 4 + 2], b3 = b[tx * 4 + 3];

#pragma unroll
    for (int i = 0; i < 4; i++) {
        int gr = row0 + ty * 4 + i;
        if (gr < n) {
            float4 o;
            o.x = acc[i][0] + b0;
            o.y = acc[i][1] + b1;
            o.z = acc[i][2] + b2;
            o.w = acc[i][3] + b3;
            *reinterpret_cast<float4*>(&g_h[(size_t)gr * OUT_F + tx * 4]) = o;
        }
    }
}

// ---------------------------------------------------------------------------
// Per-node attention halves: sl = h . a[:64], sr = h . a[64:]
// ---------------------------------------------------------------------------
__global__ __launch_bounds__(256) void slsr_kernel(
    const float* __restrict__ a, int n)
{
    int warp = (blockIdx.x * blockDim.x + threadIdx.x) >> 5;
    int lane = threadIdx.x & 31;
    if (warp >= n) return;

    float2 hv = *reinterpret_cast<const float2*>(&g_h[(size_t)warp * OUT_F + lane * 2]);
    float2 al = *reinterpret_cast<const float2*>(&a[lane * 2]);
    float2 ar = *reinterpret_cast<const float2*>(&a[OUT_F + lane * 2]);

    float s1 = hv.x * al.x + hv.y * al.y;
    float s2 = hv.x * ar.x + hv.y * ar.y;
#pragma unroll
    for (int o = 16; o; o >>= 1) {
        s1 += __shfl_xor_sync(0xFFFFFFFFu, s1, o);
        s2 += __shfl_xor_sync(0xFFFFFFFFu, s2, o);
    }
    if (lane == 0) { g_sl[warp] = s1; g_sr[warp] = s2; }
}

// ---------------------------------------------------------------------------
// Histogram: counts[src]++
// ---------------------------------------------------------------------------
__global__ void hist_kernel(const int* __restrict__ edge, int E) {
    int e = blockIdx.x * blockDim.x + threadIdx.x;
    if (e < E) atomicAdd(&g_cnt[__ldg(&edge[e])], 1);
}

// ---------------------------------------------------------------------------
// Exclusive scan of g_cnt -> g_off. 3 kernels (1024-element tiles).
// ---------------------------------------------------------------------------
__global__ __launch_bounds__(1024) void scan1_kernel(int n) {
    __shared__ int sh[1024];
    int i = blockIdx.x * 1024 + threadIdx.x;
    int v = (i < n) ? g_cnt[i] : 0;
    sh[threadIdx.x] = v;
    __syncthreads();
#pragma unroll
    for (int off = 1; off < 1024; off <<= 1) {
        int t = (threadIdx.x >= off) ? sh[threadIdx.x - off] : 0;
        __syncthreads();
        sh[threadIdx.x] += t;
        __syncthreads();
    }
    int incl = sh[threadIdx.x];
    if (i < n) g_off[i] = incl - v;          // block-local exclusive
    if (threadIdx.x == 1023) g_bsum[blockIdx.x] = incl;
}

__global__ __launch_bounds__(128) void scan2_kernel(int nb) {
    __shared__ int sh[128];
    int v = (threadIdx.x < nb) ? g_bsum[threadIdx.x] : 0;
    sh[threadIdx.x] = v;
    __syncthreads();
#pragma unroll
    for (int off = 1; off < 128; off <<= 1) {
        int t = (threadIdx.x >= off) ? sh[threadIdx.x - off] : 0;
        __syncthreads();
        sh[threadIdx.x] += t;
        __syncthreads();
    }
    if (threadIdx.x < nb) g_bsum[threadIdx.x] = sh[threadIdx.x] - v;  // exclusive
}

__global__ void scan3_kernel(int n) {
    int i = blockIdx.x * blockDim.x + threadIdx.x;
    if (i < n) {
        int o = g_off[i] + g_bsum[i >> 10];
        g_off[i] = o;
        g_cur[i] = o;
    }
}

// ---------------------------------------------------------------------------
// Scatter: compute edge weight, drop {dst, w} into CSR slot
// ---------------------------------------------------------------------------
__global__ __launch_bounds__(256) void scatter_kernel(
    const int* __restrict__ edge, int E)
{
    int e = blockIdx.x * blockDim.x + threadIdx.x;
    if (e >= E) return;

    int s = __ldg(&edge[e]);
    int d = __ldg(&edge[E + e]);

    float sc = __ldg(&g_sl[s]) + __ldg(&g_sr[d]);
    float lr = sc > 0.f ? sc : ALPHA * sc;
    float w  = __expf(-lr);

    int pos = atomicAdd(&g_cur[s], 1);
    float2 p;
    p.x = __int_as_float(d);
    p.y = w;
    g_adj[pos] = p;
}

// ---------------------------------------------------------------------------
// Aggregate (atomic-free, warp per node) + fused LayerNorm + ELU
// ---------------------------------------------------------------------------
__global__ __launch_bounds__(256) void aggregate_kernel(
    float* __restrict__ out, const float* __restrict__ gamma,
    const float* __restrict__ beta, int n)
{
    int node = (blockIdx.x * blockDim.x + threadIdx.x) >> 5;
    int lane = threadIdx.x & 31;
    if (node >= n) return;

    const int beg = g_off[node];
    const int cnt = g_cnt[node];

    float ax = 0.f, ay = 0.f;

    for (int base = 0; base < cnt; base += 32) {
        int  rem   = cnt - base;
        bool valid = lane < rem;
        float2 dw  = valid ? g_adj[beg + base + lane]
                           : make_float2(__int_as_float(0), 0.f);
        int   dd = __float_as_int(dw.x);
        float ww = dw.y;

#pragma unroll
        for (int j = 0; j < 32; j++) {
            int   dj = __shfl_sync(0xFFFFFFFFu, dd, j);
            float wj = __shfl_sync(0xFFFFFFFFu, ww, j);
            float2 hv = *reinterpret_cast<const float2*>(
                &g_h[(size_t)dj * OUT_F + lane * 2]);
            ax = fmaf(wj, hv.x, ax);
            ay = fmaf(wj, hv.y, ay);
        }
    }

    // --- fused LayerNorm (biased var) + ELU ---
    float s = ax + ay;
#pragma unroll
    for (int o = 16; o; o >>= 1) s += __shfl_xor_sync(0xFFFFFFFFu, s, o);
    float mu = s * (1.f / OUT_F);

    float c0 = ax - mu, c1 = ay - mu;
    float q = c0 * c0 + c1 * c1;
#pragma unroll
    for (int o = 16; o; o >>= 1) q += __shfl_xor_sync(0xFFFFFFFFu, q, o);
    float rs = rsqrtf(q * (1.f / OUT_F) + LN_EPS);

    float2 gg = *reinterpret_cast<const float2*>(&gamma[lane * 2]);
    float2 bb = *reinterpret_cast<const float2*>(&beta[lane * 2]);

    float y0 = c0 * rs * gg.x + bb.x;
    float y1 = c1 * rs * gg.y + bb.y;
    y0 = y0 > 0.f ? y0 : expm1f(y0);
    y1 = y1 > 0.f ? y1 : expm1f(y1);

    float2 o2; o2.x = y0; o2.y = y1;
    *reinterpret_cast<float2*>(&out[(size_t)node * OUT_F + lane * 2]) = o2;
}

// ---------------------------------------------------------------------------
extern "C" void kernel_launch(void* const* d_in, const int* in_sizes, int n_in,
                              void* d_out, int out_size)
{
    const float* x     = (const float*)d_in[0];
    const int*   edge  = (const int*)  d_in[1];
    const float* W     = (const float*)d_in[2];
    const float* b     = (const float*)d_in[3];
    const float* a     = (const float*)d_in[4];
    const float* gamma = (const float*)d_in[5];
    const float* beta  = (const float*)d_in[6];
    float* out = (float*)d_out;

    const int n = in_sizes[0] / IN_F;   // 100000
    const int E = in_sizes[1] / 2;      // 3200000

    // CSR build pipeline (independent of gemm until scatter needs sl/sr)
    zero_cnt_kernel<<<(n + 255) / 256, 256>>>(n);
    gemm_kernel<<<(n + 63) / 64, 256>>>(x, W, b, n);
    slsr_kernel<<<(n + 7) / 8, 256>>>(a, n);
    hist_kernel<<<(E + 255) / 256, 256>>>(edge, E);

    int nb = (n + 1023) / 1024;
    scan1_kernel<<<nb, 1024>>>(n);
    scan2_kernel<<<1, 128>>>(nb);
    scan3_kernel<<<(n + 255) / 256, 256>>>(n);

    scatter_kernel<<<(E + 255) / 256, 256>>>(edge, E);

    aggregate_kernel<<<(n + 7) / 8, 256>>>(out, gamma, beta, n);
}

// round 3
// speedup vs baseline: 1.2826x; 1.0807x over previous
#include <cuda_runtime.h>

#define IN_F   128
#define OUT_F  64
#define ALPHA  0.2f
#define LN_EPS 1e-5f
#define MAXN   100352    // padded above N=100000 (multiple of 1024)
#define EMAX   3276800   // padded above E=3200000

// Scratch (device globals — no allocation allowed)
__device__ float  g_h [MAXN * OUT_F];  // h = x@W^T + b
__device__ float  g_sl[MAXN];          // h @ a[:64]
__device__ float  g_sr[MAXN];          // h @ a[64:]
__device__ int    g_cnt[MAXN];         // per-src edge counts
__device__ int    g_off[MAXN];         // exclusive prefix (CSR row ptr)
__device__ int    g_cur[MAXN];         // scatter cursors (copy of g_off)
__device__ int    g_bsum[128];         // block sums for scan
__device__ float2 g_adj[EMAX];         // CSR payload: {dst (int bits), weight}

// ---------------------------------------------------------------------------
__global__ void zero_cnt_kernel(int n) {
    int i = blockIdx.x * blockDim.x + threadIdx.x;
    if (i < n) g_cnt[i] = 0;
}

// ---------------------------------------------------------------------------
// GEMM: h[n,64] = x[n,128] @ W[64,128]^T + b, fused sl/sr epilogue.
// Block 256 threads: 128-row x 64-col tile, 8x4 register microtile,
// k-chunked smem (32 at a time), W kept transposed for float4 LDS.
// ---------------------------------------------------------------------------
__global__ __launch_bounds__(256) void gemm_kernel(
    const float* __restrict__ x, const float* __restrict__ W,
    const float* __restrict__ b, const float* __restrict__ a, int n)
{
    __shared__ float xs[128][33];        // [row][k within chunk]
    __shared__ float wsT[32][64];        // [k within chunk][col]

    const int tid  = threadIdx.x;
    const int row0 = blockIdx.x * 128;
    const int tx   = tid & 15;           // col group: cols tx*4 .. tx*4+3
    const int ty   = tid >> 4;           // row group: rows ty*8 .. ty*8+7

    float acc[8][4];
#pragma unroll
    for (int i = 0; i < 8; i++)
#pragma unroll
        for (int j = 0; j < 4; j++) acc[i][j] = 0.f;

    for (int kc = 0; kc < IN_F; kc += 32) {
        // x chunk: 128 rows x 32 k (1024 float4 loads, 4 per thread)
#pragma unroll
        for (int i = 0; i < 4; i++) {
            int f4 = tid + i * 256;          // 0..1023
            int r  = f4 >> 3;                // 8 float4 per row
            int k4 = (f4 & 7) << 2;
            int gr = row0 + r;
            float4 v = make_float4(0.f, 0.f, 0.f, 0.f);
            if (gr < n)
                v = *reinterpret_cast<const float4*>(&x[(size_t)gr * IN_F + kc + k4]);
            xs[r][k4 + 0] = v.x; xs[r][k4 + 1] = v.y;
            xs[r][k4 + 2] = v.z; xs[r][k4 + 3] = v.w;
        }
        // W chunk, transposed: wsT[kk][c] = W[c][kc+kk] (2048 scalars, 8/thread)
#pragma unroll
        for (int i = 0; i < 8; i++) {
            int idx = tid + i * 256;         // 0..2047
            int kk  = idx >> 6;              // 0..31
            int c   = idx & 63;              // 0..63
            wsT[kk][c] = W[c * IN_F + kc + kk];
        }
        __syncthreads();

#pragma unroll
        for (int kk = 0; kk < 32; kk++) {
            float4 wv = *reinterpret_cast<const float4*>(&wsT[kk][tx * 4]);
            float xv[8];
#pragma unroll
            for (int i = 0; i < 8; i++) xv[i] = xs[ty * 8 + i][kk];
#pragma unroll
            for (int i = 0; i < 8; i++) {
                acc[i][0] = fmaf(xv[i], wv.x, acc[i][0]);
                acc[i][1] = fmaf(xv[i], wv.y, acc[i][1]);
                acc[i][2] = fmaf(xv[i], wv.z, acc[i][2]);
                acc[i][3] = fmaf(xv[i], wv.w, acc[i][3]);
            }
        }
        __syncthreads();
    }

    // Epilogue: +bias, store h, fused sl/sr (reduce over the 16 tx lanes —
    // lane = (ty&1)*16 + tx, so xor offsets <=8 stay inside the half-warp).
    float4 bv  = *reinterpret_cast<const float4*>(&b[tx * 4]);
    float4 alv = *reinterpret_cast<const float4*>(&a[tx * 4]);
    float4 arv = *reinterpret_cast<const float4*>(&a[OUT_F + tx * 4]);

#pragma unroll
    for (int i = 0; i < 8; i++) {
        int gr = row0 + ty * 8 + i;
        float4 o;
        o.x = acc[i][0] + bv.x;
        o.y = acc[i][1] + bv.y;
        o.z = acc[i][2] + bv.z;
        o.w = acc[i][3] + bv.w;

        float pl = o.x * alv.x + o.y * alv.y + o.z * alv.z + o.w * alv.w;
        float pr = o.x * arv.x + o.y * arv.y + o.z * arv.z + o.w * arv.w;
#pragma unroll
        for (int off = 8; off; off >>= 1) {
            pl += __shfl_xor_sync(0xFFFFFFFFu, pl, off);
            pr += __shfl_xor_sync(0xFFFFFFFFu, pr, off);
        }

        if (gr < n) {
            *reinterpret_cast<float4*>(&g_h[(size_t)gr * OUT_F + tx * 4]) = o;
            if (tx == 0) { g_sl[gr] = pl; g_sr[gr] = pr; }
        }
    }
}

// ---------------------------------------------------------------------------
// Histogram: counts[src]++, 4 edges per thread (int4) for MLP
// ---------------------------------------------------------------------------
__global__ void hist_kernel(const int* __restrict__ edge, int E) {
    int t = blockIdx.x * blockDim.x + threadIdx.x;
    int e = t * 4;
    if (e + 3 < E) {
        int4 s = *reinterpret_cast<const int4*>(&edge[e]);
        atomicAdd(&g_cnt[s.x], 1);
        atomicAdd(&g_cnt[s.y], 1);
        atomicAdd(&g_cnt[s.z], 1);
        atomicAdd(&g_cnt[s.w], 1);
    } else {
        for (int q = e; q < E; q++) atomicAdd(&g_cnt[edge[q]], 1);
    }
}

// ---------------------------------------------------------------------------
// Exclusive scan of g_cnt -> g_off (3 kernels, 1024-element tiles)
// ---------------------------------------------------------------------------
__global__ __launch_bounds__(1024) void scan1_kernel(int n) {
    __shared__ int sh[1024];
    int i = blockIdx.x * 1024 + threadIdx.x;
    int v = (i < n) ? g_cnt[i] : 0;
    sh[threadIdx.x] = v;
    __syncthreads();
#pragma unroll
    for (int off = 1; off < 1024; off <<= 1) {
        int t = (threadIdx.x >= off) ? sh[threadIdx.x - off] : 0;
        __syncthreads();
        sh[threadIdx.x] += t;
        __syncthreads();
    }
    int incl = sh[threadIdx.x];
    if (i < n) g_off[i] = incl - v;
    if (threadIdx.x == 1023) g_bsum[blockIdx.x] = incl;
}

__global__ __launch_bounds__(128) void scan2_kernel(int nb) {
    __shared__ int sh[128];
    int v = (threadIdx.x < nb) ? g_bsum[threadIdx.x] : 0;
    sh[threadIdx.x] = v;
    __syncthreads();
#pragma unroll
    for (int off = 1; off < 128; off <<= 1) {
        int t = (threadIdx.x >= off) ? sh[threadIdx.x - off] : 0;
        __syncthreads();
        sh[threadIdx.x] += t;
        __syncthreads();
    }
    if (threadIdx.x < nb) g_bsum[threadIdx.x] = sh[threadIdx.x] - v;
}

__global__ void scan3_kernel(int n) {
    int i = blockIdx.x * blockDim.x + threadIdx.x;
    if (i < n) {
        int o = g_off[i] + g_bsum[i >> 10];
        g_off[i] = o;
        g_cur[i] = o;
    }
}

// ---------------------------------------------------------------------------
// Scatter: per-edge weight into CSR slot, 4 edges per thread
// ---------------------------------------------------------------------------
__global__ __launch_bounds__(256) void scatter_kernel(
    const int* __restrict__ edge, int E)
{
    int t = blockIdx.x * blockDim.x + threadIdx.x;
    int e = t * 4;

    if (e + 3 < E) {
        int4 s4 = *reinterpret_cast<const int4*>(&edge[e]);
        int4 d4 = *reinterpret_cast<const int4*>(&edge[E + e]);
        int s[4] = {s4.x, s4.y, s4.z, s4.w};
        int d[4] = {d4.x, d4.y, d4.z, d4.w};
        float slv[4], srv[4];
#pragma unroll
        for (int q = 0; q < 4; q++) { slv[q] = __ldg(&g_sl[s[q]]); srv[q] = __ldg(&g_sr[d[q]]); }
#pragma unroll
        for (int q = 0; q < 4; q++) {
            float sc = slv[q] + srv[q];
            float lr = sc > 0.f ? sc : ALPHA * sc;
            float w  = __expf(-lr);
            int pos = atomicAdd(&g_cur[s[q]], 1);
            float2 p; p.x = __int_as_float(d[q]); p.y = w;
            g_adj[pos] = p;
        }
    } else {
        for (int q = e; q < E; q++) {
            int s = edge[q], d = edge[E + q];
            float sc = g_sl[s] + g_sr[d];
            float lr = sc > 0.f ? sc : ALPHA * sc;
            float w  = __expf(-lr);
            int pos = atomicAdd(&g_cur[s], 1);
            float2 p; p.x = __int_as_float(d); p.y = w;
            g_adj[pos] = p;
        }
    }
}

// ---------------------------------------------------------------------------
// Aggregate (atomic-free, warp per node) + fused LayerNorm + ELU
// ---------------------------------------------------------------------------
__global__ __launch_bounds__(256) void aggregate_kernel(
    float* __restrict__ out, const float* __restrict__ gamma,
    const float* __restrict__ beta, int n)
{
    int node = (blockIdx.x * blockDim.x + threadIdx.x) >> 5;
    int lane = threadIdx.x & 31;
    if (node >= n) return;

    const int beg = __ldg(&g_off[node]);
    const int cnt = __ldg(&g_cnt[node]);

    float ax0 = 0.f, ay0 = 0.f, ax1 = 0.f, ay1 = 0.f;

    for (int base = 0; base < cnt; base += 32) {
        int  rem   = cnt - base;
        bool valid = lane < rem;
        float2 dw  = valid ? g_adj[beg + base + lane]
                           : make_float2(__int_as_float(0), 0.f);
        int   dd = __float_as_int(dw.x);
        float ww = dw.y;

#pragma unroll
        for (int j = 0; j < 32; j += 2) {
            int   d0 = __shfl_sync(0xFFFFFFFFu, dd, j);
            float w0 = __shfl_sync(0xFFFFFFFFu, ww, j);
            int   d1 = __shfl_sync(0xFFFFFFFFu, dd, j + 1);
            float w1 = __shfl_sync(0xFFFFFFFFu, ww, j + 1);
            float2 h0 = *reinterpret_cast<const float2*>(
                &g_h[(size_t)d0 * OUT_F + lane * 2]);
            float2 h1 = *reinterpret_cast<const float2*>(
                &g_h[(size_t)d1 * OUT_F + lane * 2]);
            ax0 = fmaf(w0, h0.x, ax0);
            ay0 = fmaf(w0, h0.y, ay0);
            ax1 = fmaf(w1, h1.x, ax1);
            ay1 = fmaf(w1, h1.y, ay1);
        }
    }

    float ax = ax0 + ax1, ay = ay0 + ay1;

    // --- fused LayerNorm (biased var) + ELU ---
    float s = ax + ay;
#pragma unroll
    for (int o = 16; o; o >>= 1) s += __shfl_xor_sync(0xFFFFFFFFu, s, o);
    float mu = s * (1.f / OUT_F);

    float c0 = ax - mu, c1 = ay - mu;
    float q = c0 * c0 + c1 * c1;
#pragma unroll
    for (int o = 16; o; o >>= 1) q += __shfl_xor_sync(0xFFFFFFFFu, q, o);
    float rs = rsqrtf(q * (1.f / OUT_F) + LN_EPS);

    float2 gg = *reinterpret_cast<const float2*>(&gamma[lane * 2]);
    float2 bb = *reinterpret_cast<const float2*>(&beta[lane * 2]);

    float y0 = c0 * rs * gg.x + bb.x;
    float y1 = c1 * rs * gg.y + bb.y;
    y0 = y0 > 0.f ? y0 : expm1f(y0);
    y1 = y1 > 0.f ? y1 : expm1f(y1);

    float2 o2; o2.x = y0; o2.y = y1;
    *reinterpret_cast<float2*>(&out[(size_t)node * OUT_F + lane * 2]) = o2;
}

// ---------------------------------------------------------------------------
extern "C" void kernel_launch(void* const* d_in, const int* in_sizes, int n_in,
                              void* d_out, int out_size)
{
    const float* x     = (const float*)d_in[0];
    const int*   edge  = (const int*)  d_in[1];
    const float* W     = (const float*)d_in[2];
    const float* b     = (const float*)d_in[3];
    const float* a     = (const float*)d_in[4];
    const float* gamma = (const float*)d_in[5];
    const float* beta  = (const float*)d_in[6];
    float* out = (float*)d_out;

    const int n = in_sizes[0] / IN_F;   // 100000
    const int E = in_sizes[1] / 2;      // 3200000

    zero_cnt_kernel<<<(n + 255) / 256, 256>>>(n);
    gemm_kernel<<<(n + 127) / 128, 256>>>(x, W, b, a, n);

    int t4 = (E + 3) / 4;
    hist_kernel<<<(t4 + 255) / 256, 256>>>(edge, E);

    int nb = (n + 1023) / 1024;
    scan1_kernel<<<nb, 1024>>>(n);
    scan2_kernel<<<1, 128>>>(nb);
    scan3_kernel<<<(n + 255) / 256, 256>>>(n);

    scatter_kernel<<<(t4 + 255) / 256, 256>>>(edge, E);

    aggregate_kernel<<<(n + 7) / 8, 256>>>(out, gamma, beta, n);
}

// round 5
// speedup vs baseline: 1.3280x; 1.0354x over previous
#include <cuda_runtime.h>
#include <cuda_fp16.h>
#include <cstdint>

#define IN_F   128
#define OUT_F  64
#define ALPHA  0.2f
#define LN_EPS 1e-5f
#define MAXN   100352    // padded above N=100000 (multiple of 1024)
#define EMAX   3276800   // padded above E=3200000

// Scratch (device globals — no allocation allowed)
__device__ __half2 g_hh[MAXN * 32];   // h in fp16 (only consumer: aggregate gather)
__device__ float   g_sl[MAXN];        // h @ a[:64]
__device__ float   g_sr[MAXN];        // h @ a[64:]
__device__ int     g_cnt[MAXN];       // per-src edge counts
__device__ int     g_off[MAXN];       // exclusive prefix (CSR row ptr)
__device__ int     g_cur[MAXN];       // scatter cursors
__device__ int     g_bsum[128];       // block sums for scan
__device__ int     g_adj[EMAX];       // CSR payload: dst only (4 B/edge)

// ---------------------------------------------------------------------------
__global__ void zero_cnt_kernel(int n) {
    int i = blockIdx.x * blockDim.x + threadIdx.x;
    if (i < n) g_cnt[i] = 0;
}

// ---------------------------------------------------------------------------
// GEMM: h[n,64] = x[n,128] @ W[64,128]^T + b; writes fp16 h + fused sl/sr.
// ---------------------------------------------------------------------------
__global__ __launch_bounds__(256) void gemm_kernel(
    const float* __restrict__ x, const float* __restrict__ W,
    const float* __restrict__ b, const float* __restrict__ a, int n)
{
    __shared__ float xs[128][33];
    __shared__ float wsT[32][64];

    const int tid  = threadIdx.x;
    const int row0 = blockIdx.x * 128;
    const int tx   = tid & 15;           // cols tx*4 .. tx*4+3
    const int ty   = tid >> 4;           // rows ty*8 .. ty*8+7

    float acc[8][4];
#pragma unroll
    for (int i = 0; i < 8; i++)
#pragma unroll
        for (int j = 0; j < 4; j++) acc[i][j] = 0.f;

    for (int kc = 0; kc < IN_F; kc += 32) {
#pragma unroll
        for (int i = 0; i < 4; i++) {
            int f4 = tid + i * 256;
            int r  = f4 >> 3;
            int k4 = (f4 & 7) << 2;
            int gr = row0 + r;
            float4 v = make_float4(0.f, 0.f, 0.f, 0.f);
            if (gr < n)
                v = *reinterpret_cast<const float4*>(&x[(size_t)gr * IN_F + kc + k4]);
            xs[r][k4 + 0] = v.x; xs[r][k4 + 1] = v.y;
            xs[r][k4 + 2] = v.z; xs[r][k4 + 3] = v.w;
        }
#pragma unroll
        for (int i = 0; i < 8; i++) {
            int idx = tid + i * 256;
            int kk  = idx >> 6;
            int c   = idx & 63;
            wsT[kk][c] = W[c * IN_F + kc + kk];
        }
        __syncthreads();

#pragma unroll
        for (int kk = 0; kk < 32; kk++) {
            float4 wv = *reinterpret_cast<const float4*>(&wsT[kk][tx * 4]);
            float xv[8];
#pragma unroll
            for (int i = 0; i < 8; i++) xv[i] = xs[ty * 8 + i][kk];
#pragma unroll
            for (int i = 0; i < 8; i++) {
                acc[i][0] = fmaf(xv[i], wv.x, acc[i][0]);
                acc[i][1] = fmaf(xv[i], wv.y, acc[i][1]);
                acc[i][2] = fmaf(xv[i], wv.z, acc[i][2]);
                acc[i][3] = fmaf(xv[i], wv.w, acc[i][3]);
            }
        }
        __syncthreads();
    }

    float4 bv  = *reinterpret_cast<const float4*>(&b[tx * 4]);
    float4 alv = *reinterpret_cast<const float4*>(&a[tx * 4]);
    float4 arv = *reinterpret_cast<const float4*>(&a[OUT_F + tx * 4]);

#pragma unroll
    for (int i = 0; i < 8; i++) {
        int gr = row0 + ty * 8 + i;
        float4 o;
        o.x = acc[i][0] + bv.x;
        o.y = acc[i][1] + bv.y;
        o.z = acc[i][2] + bv.z;
        o.w = acc[i][3] + bv.w;

        float pl = o.x * alv.x + o.y * alv.y + o.z * alv.z + o.w * alv.w;
        float pr = o.x * arv.x + o.y * arv.y + o.z * arv.z + o.w * arv.w;
#pragma unroll
        for (int off = 8; off; off >>= 1) {
            pl += __shfl_xor_sync(0xFFFFFFFFu, pl, off);
            pr += __shfl_xor_sync(0xFFFFFFFFu, pr, off);
        }

        if (gr < n) {
            g_hh[(size_t)gr * 32 + tx * 2 + 0] = __floats2half2_rn(o.x, o.y);
            g_hh[(size_t)gr * 32 + tx * 2 + 1] = __floats2half2_rn(o.z, o.w);
            if (tx == 0) { g_sl[gr] = pl; g_sr[gr] = pr; }
        }
    }
}

// ---------------------------------------------------------------------------
// Histogram: counts[src]++, 4 edges per thread for MLP
// ---------------------------------------------------------------------------
__global__ void hist_kernel(const int* __restrict__ edge, int E) {
    int t = blockIdx.x * blockDim.x + threadIdx.x;
    int e = t * 4;
    if (e + 3 < E) {
        int4 s = *reinterpret_cast<const int4*>(&edge[e]);
        atomicAdd(&g_cnt[s.x], 1);
        atomicAdd(&g_cnt[s.y], 1);
        atomicAdd(&g_cnt[s.z], 1);
        atomicAdd(&g_cnt[s.w], 1);
    } else {
        for (int q = e; q < E; q++) atomicAdd(&g_cnt[edge[q]], 1);
    }
}

// ---------------------------------------------------------------------------
// Exclusive scan of g_cnt -> g_off (shuffle-based, 2 barriers)
// ---------------------------------------------------------------------------
__global__ __launch_bounds__(1024) void scan1_kernel(int n) {
    __shared__ int ws[32];
    int tid  = threadIdx.x;
    int lane = tid & 31;
    int wid  = tid >> 5;
    int i = blockIdx.x * 1024 + tid;
    int v = (i < n) ? g_cnt[i] : 0;

    int s = v;
#pragma unroll
    for (int off = 1; off < 32; off <<= 1) {
        int t = __shfl_up_sync(0xFFFFFFFFu, s, off);
        if (lane >= off) s += t;
    }
    if (lane == 31) ws[wid] = s;
    __syncthreads();
    if (wid == 0) {
        int t = ws[lane];
        int u = t;
#pragma unroll
        for (int off = 1; off < 32; off <<= 1) {
            int z = __shfl_up_sync(0xFFFFFFFFu, u, off);
            if (lane >= off) u += z;
        }
        ws[lane] = u - t;                       // exclusive warp prefix
        if (lane == 31) g_bsum[blockIdx.x] = u; // block total
    }
    __syncthreads();
    if (i < n) g_off[i] = s - v + ws[wid];
}

__global__ __launch_bounds__(128) void scan2_kernel(int nb) {
    __shared__ int ws[4];
    int tid  = threadIdx.x;
    int lane = tid & 31;
    int wid  = tid >> 5;
    int v = (tid < nb) ? g_bsum[tid] : 0;

    int s = v;
#pragma unroll
    for (int off = 1; off < 32; off <<= 1) {
        int t = __shfl_up_sync(0xFFFFFFFFu, s, off);
        if (lane >= off) s += t;
    }
    if (lane == 31) ws[wid] = s;
    __syncthreads();
    int wadd = 0;
    for (int w = 0; w < wid; w++) wadd += ws[w];
    if (tid < nb) g_bsum[tid] = s - v + wadd;   // exclusive
}

__global__ void scan3_kernel(int n) {
    int i = blockIdx.x * blockDim.x + threadIdx.x;
    if (i < n) {
        int o = g_off[i] + g_bsum[i >> 10];
        g_off[i] = o;
        g_cur[i] = o;
    }
}

// ---------------------------------------------------------------------------
// Scatter: drop dst into CSR slot, 4 edges/thread (no weight math here)
// ---------------------------------------------------------------------------
__global__ __launch_bounds__(256) void scatter_kernel(
    const int* __restrict__ edge, int E)
{
    int t = blockIdx.x * blockDim.x + threadIdx.x;
    int e = t * 4;

    if (e + 3 < E) {
        int4 s4 = *reinterpret_cast<const int4*>(&edge[e]);
        int4 d4 = *reinterpret_cast<const int4*>(&edge[E + e]);
        int p0 = atomicAdd(&g_cur[s4.x], 1);
        int p1 = atomicAdd(&g_cur[s4.y], 1);
        int p2 = atomicAdd(&g_cur[s4.z], 1);
        int p3 = atomicAdd(&g_cur[s4.w], 1);
        g_adj[p0] = d4.x;
        g_adj[p1] = d4.y;
        g_adj[p2] = d4.z;
        g_adj[p3] = d4.w;
    } else {
        for (int q = e; q < E; q++) {
            int pos = atomicAdd(&g_cur[edge[q]], 1);
            g_adj[pos] = edge[E + q];
        }
    }
}

// ---------------------------------------------------------------------------
// Aggregate (atomic-free, warp per node): weight computed in-flight,
// fp16 h gather, fused LayerNorm + ELU.
// ---------------------------------------------------------------------------
__global__ __launch_bounds__(256) void aggregate_kernel(
    float* __restrict__ out, const float* __restrict__ gamma,
    const float* __restrict__ beta, int n)
{
    int node = (blockIdx.x * blockDim.x + threadIdx.x) >> 5;
    int lane = threadIdx.x & 31;
    if (node >= n) return;

    const int   beg  = __ldg(&g_off[node]);
    const int   cnt  = __ldg(&g_cnt[node]);
    const float sl_n = __ldg(&g_sl[node]);

    float ax0 = 0.f, ay0 = 0.f, ax1 = 0.f, ay1 = 0.f;

    for (int base = 0; base < cnt; base += 32) {
        bool valid = (base + lane) < cnt;
        int   dd = valid ? __ldg(&g_adj[beg + base + lane]) : 0;
        float ww = 0.f;
        if (valid) {
            float sc = sl_n + __ldg(&g_sr[dd]);
            float lr = sc > 0.f ? sc : ALPHA * sc;
            ww = __expf(-lr);
        }

#pragma unroll
        for (int j = 0; j < 32; j += 2) {
            int   d0 = __shfl_sync(0xFFFFFFFFu, dd, j);
            float w0 = __shfl_sync(0xFFFFFFFFu, ww, j);
            int   d1 = __shfl_sync(0xFFFFFFFFu, dd, j + 1);
            float w1 = __shfl_sync(0xFFFFFFFFu, ww, j + 1);
            __half2 h0 = g_hh[(size_t)d0 * 32 + lane];
            __half2 h1 = g_hh[(size_t)d1 * 32 + lane];
            float2 f0 = __half22float2(h0);
            float2 f1 = __half22float2(h1);
            ax0 = fmaf(w0, f0.x, ax0);
            ay0 = fmaf(w0, f0.y, ay0);
            ax1 = fmaf(w1, f1.x, ax1);
            ay1 = fmaf(w1, f1.y, ay1);
        }
    }

    float ax = ax0 + ax1, ay = ay0 + ay1;

    // --- fused LayerNorm (biased var) + ELU ---
    float s = ax + ay;
#pragma unroll
    for (int o = 16; o; o >>= 1) s += __shfl_xor_sync(0xFFFFFFFFu, s, o);
    float mu = s * (1.f / OUT_F);

    float c0 = ax - mu, c1 = ay - mu;
    float q = c0 * c0 + c1 * c1;
#pragma unroll
    for (int o = 16; o; o >>= 1) q += __shfl_xor_sync(0xFFFFFFFFu, q, o);
    float rs = rsqrtf(q * (1.f / OUT_F) + LN_EPS);

    float2 gg = *reinterpret_cast<const float2*>(&gamma[lane * 2]);
    float2 bb = *reinterpret_cast<const float2*>(&beta[lane * 2]);

    float y0 = c0 * rs * gg.x + bb.x;
    float y1 = c1 * rs * gg.y + bb.y;
    y0 = y0 > 0.f ? y0 : expm1f(y0);
    y1 = y1 > 0.f ? y1 : expm1f(y1);

    float2 o2; o2.x = y0; o2.y = y1;
    *reinterpret_cast<float2*>(&out[(size_t)node * OUT_F + lane * 2]) = o2;
}

// ---------------------------------------------------------------------------
extern "C" void kernel_launch(void* const* d_in, const int* in_sizes, int n_in,
                              void* d_out, int out_size)
{
    const float* x     = (const float*)d_in[0];
    const int*   edge  = (const int*)  d_in[1];
    const float* W     = (const float*)d_in[2];
    const float* b     = (const float*)d_in[3];
    const float* a     = (const float*)d_in[4];
    const float* gamma = (const float*)d_in[5];
    const float* beta  = (const float*)d_in[6];
    float* out = (float*)d_out;

    const int n = in_sizes[0] / IN_F;   // 100000
    const int E = in_sizes[1] / 2;      // 3200000

    zero_cnt_kernel<<<(n + 255) / 256, 256>>>(n);
    gemm_kernel<<<(n + 127) / 128, 256>>>(x, W, b, a, n);

    int t4 = (E + 3) / 4;
    hist_kernel<<<(t4 + 255) / 256, 256>>>(edge, E);

    int nb = (n + 1023) / 1024;
    scan1_kernel<<<nb, 1024>>>(n);
    scan2_kernel<<<1, 128>>>(nb);
    scan3_kernel<<<(n + 255) / 256, 256>>>(n);

    scatter_kernel<<<(t4 + 255) / 256, 256>>>(edge, E);

    aggregate_kernel<<<(n + 7) / 8, 256>>>(out, gamma, beta, n);
}